// round 1
// baseline (speedup 1.0000x reference)
#include <cuda_runtime.h>
#include <cstdint>

// ---------------- scratch (device globals; no allocations allowed) ----------
// y: basis-expanded, zero... NOT zero-padded: pad locations hold bases(0.0f),
// matching reference (pad happens BEFORE basis expansion).
// layout: [b][c=i*8+g][hp(34)][wp(34)]
__device__ float g_y[16 * 512 * 34 * 34];      // ~37.9 MB
// folded weights: [c=i*8+g][tap=k*3+l][o], o contiguous
__device__ float g_w2[512 * 9 * 64];           // ~1.15 MB

static constexpr int B = 16, CIN = 64, H = 32, W = 32, COUT = 64;
static constexpr int GS = 8;                   // grid_size + spline_order
static constexpr int HP = 34, WP = 34;         // padded
static constexpr int CK = CIN * GS;            // 512 effective input channels

// ---------------- f32x2 helpers (sm_100+) -----------------------------------
__device__ __forceinline__ unsigned long long pack2(float lo, float hi) {
    unsigned long long r;
    asm("mov.b64 %0, {%1, %2};" : "=l"(r) : "f"(lo), "f"(hi));
    return r;
}
__device__ __forceinline__ void fma2(unsigned long long& d,
                                     unsigned long long a,
                                     unsigned long long b) {
    asm("fma.rn.f32x2 %0, %1, %2, %0;" : "+l"(d) : "l"(a), "l"(b));
}
__device__ __forceinline__ void unpack2(unsigned long long v, float& lo, float& hi) {
    asm("mov.b64 {%0, %1}, %2;" : "=f"(lo), "=f"(hi) : "l"(v));
}

// ---------------- kernel 1: fold scaler into spline weight, relayout --------
// w2[((i*8+g)*9 + tap)*64 + o] = sw[o][i][g][tap] * sc[o][i]
__global__ void wprep_kernel(const float* __restrict__ sw,
                             const float* __restrict__ sc) {
    int t = blockIdx.x * blockDim.x + threadIdx.x;
    if (t >= CK * 9 * COUT) return;
    int o = t & 63;
    int r = t >> 6;
    int tap = r % 9; r /= 9;
    int g = r & 7;
    int i = r >> 3;
    g_w2[t] = sw[((o * CIN + i) * GS + g) * 9 + tap] * sc[o * CIN + i];
}

// ---------------- kernel 2: B-spline basis expansion -------------------------
// One thread per padded location (b, i, hp, wp); writes 8 basis planes.
__global__ void basis_kernel(const float* __restrict__ x) {
    int idx = blockIdx.x * blockDim.x + threadIdx.x;
    if (idx >= B * CIN * HP * WP) return;
    int wp = idx % WP;
    int t = idx / WP;
    int hp = t % HP; t /= HP;
    int i = t % CIN;
    int b = t / CIN;

    float xv = 0.0f;
    int h = hp - 1, w = wp - 1;
    if ((unsigned)h < (unsigned)H && (unsigned)w < (unsigned)W)
        xv = x[((b * CIN + i) * H + h) * W + w];

    // knots: t_j = float(j-3)*0.4f - 1.0f, j = 0..11 (matches reference exactly)
    float gk[12];
#pragma unroll
    for (int j = 0; j < 12; j++) gk[j] = (float)(j - 3) * 0.4f - 1.0f;

    float b0[11];
#pragma unroll
    for (int j = 0; j < 11; j++)
        b0[j] = (xv >= gk[j] && xv < gk[j + 1]) ? 1.0f : 0.0f;
    float b1[10];
#pragma unroll
    for (int j = 0; j < 10; j++)
        b1[j] = ((xv - gk[j]) * b0[j] + (gk[j + 2] - xv) * b0[j + 1]) * 2.5f;
    float b2[9];
#pragma unroll
    for (int j = 0; j < 9; j++)
        b2[j] = ((xv - gk[j]) * b1[j] + (gk[j + 3] - xv) * b1[j + 1]) * 1.25f;
    float b3[8];
#pragma unroll
    for (int j = 0; j < 8; j++)
        b3[j] = ((xv - gk[j]) * b2[j] + (gk[j + 4] - xv) * b2[j + 1]) * (1.0f / 1.2f);

    int base = ((b * CIN + i) * GS) * (HP * WP) + hp * WP + wp;
#pragma unroll
    for (int g = 0; g < GS; g++) g_y[base + g * (HP * WP)] = b3[g];
}

// ---------------- kernel 3: implicit-GEMM conv (f32x2 math) ------------------
// Block: one batch b, 2 output rows, all 64 Cout. 256 threads.
// Thread (tx = tid&15, ty = tid>>4): 4 pixels (same row, 4 consecutive cols)
//   x 4 channels (n0 = tx*4). Channel pairs ride the f32x2 lanes.
static constexpr int CC = 8;  // channels per smem stage

__global__ __launch_bounds__(256) void conv_kernel(float* __restrict__ out) {
    __shared__ __align__(16) float As[CC][4][36];       // [c][row][col<=33]
    __shared__ __align__(16) float Bs[CC][9][COUT];     // [c][tap][o]

    int blk = blockIdx.x;             // 0..255
    int b = blk >> 4;
    int h0 = (blk & 15) * 2;          // output row base
    int tid = threadIdx.x;
    int tx = tid & 15, ty = tid >> 4;
    int pr = ty >> 3;                 // pixel row within tile (0/1)
    int c0 = (ty & 7) * 4;            // pixel col base
    int n0 = tx * 4;                  // channel base

    unsigned long long acc[4][2];     // [pixel m][channel-pair n2]
#pragma unroll
    for (int m = 0; m < 4; m++) { acc[m][0] = 0ull; acc[m][1] = 0ull; }

    const float* ybase = g_y + (size_t)b * CK * (HP * WP);

    for (int cc = 0; cc < CK; cc += CC) {
        // stage A: CC x 4 rows x 34 cols
        for (int t2 = tid; t2 < CC * 4 * 34; t2 += 256) {
            int col = t2 % 34;
            int rr = t2 / 34;
            int row = rr & 3;
            int c = rr >> 2;
            As[c][row][col] = ybase[(cc + c) * (HP * WP) + (h0 + row) * WP + col];
        }
        // stage B: CC x 9 x 64 floats, contiguous in g_w2 -> float4 copies
        {
            const float4* wsrc = (const float4*)(g_w2 + cc * 9 * COUT);
            float4* bdst = (float4*)(&Bs[0][0][0]);
            for (int t2 = tid; t2 < CC * 9 * (COUT / 4); t2 += 256)
                bdst[t2] = wsrc[t2];
        }
        __syncthreads();

#pragma unroll
        for (int c = 0; c < CC; c++) {
#pragma unroll
            for (int k = 0; k < 3; k++) {
                float ar[6];
#pragma unroll
                for (int j = 0; j < 6; j++) ar[j] = As[c][pr + k][c0 + j];
                unsigned long long ab[6];
#pragma unroll
                for (int j = 0; j < 6; j++) ab[j] = pack2(ar[j], ar[j]);
#pragma unroll
                for (int l = 0; l < 3; l++) {
                    ulonglong2 wv =
                        *(const ulonglong2*)&Bs[c][k * 3 + l][n0];
#pragma unroll
                    for (int m = 0; m < 4; m++) {
                        fma2(acc[m][0], ab[l + m], wv.x);
                        fma2(acc[m][1], ab[l + m], wv.y);
                    }
                }
            }
        }
        __syncthreads();
    }

    // write out[b][n][h0+pr][c0..c0+3]
    int orow = h0 + pr;
#pragma unroll
    for (int n2 = 0; n2 < 2; n2++) {
        float lo[4], hi[4];
#pragma unroll
        for (int m = 0; m < 4; m++) unpack2(acc[m][n2], lo[m], hi[m]);
        int nA = n0 + 2 * n2;
        float4* dstA = (float4*)&out[((b * COUT + nA) * H + orow) * W + c0];
        float4* dstB = (float4*)&out[((b * COUT + nA + 1) * H + orow) * W + c0];
        *dstA = make_float4(lo[0], lo[1], lo[2], lo[3]);
        *dstB = make_float4(hi[0], hi[1], hi[2], hi[3]);
    }
}

// ---------------- launch ------------------------------------------------------
extern "C" void kernel_launch(void* const* d_in, const int* in_sizes, int n_in,
                              void* d_out, int out_size) {
    const float* x  = (const float*)d_in[0];   // [16,64,32,32]
    const float* sw = (const float*)d_in[1];   // [64,64,8,3,3]
    const float* sc = (const float*)d_in[2];   // [64,64]
    float* out = (float*)d_out;                // [16,64,32,32]

    {
        int n = CK * 9 * COUT;
        wprep_kernel<<<(n + 255) / 256, 256>>>(sw, sc);
    }
    {
        int n = B * CIN * HP * WP;
        basis_kernel<<<(n + 255) / 256, 256>>>(x);
    }
    conv_kernel<<<B * (H / 2), 256>>>(out);
}

// round 5
// speedup vs baseline: 3.1082x; 3.1082x over previous
#include <cuda_runtime.h>
#include <cuda_bf16.h>
#include <cstdint>

// ---------------- problem constants -----------------------------------------
static constexpr int BB = 16, CIN = 64, H = 32, W = 32, COUT = 64;
static constexpr int GS = 8;                  // grid_size + spline_order
static constexpr int HP = 34, WP = 34;        // padded spatial
static constexpr int CK = CIN * GS;           // 512 effective channels

// ---------------- device scratch (no allocations allowed) -------------------
// basis planes, channel-last: [b][hp][wp][c=i*8+g], bf16 hi and lo parts
__device__ __align__(16) __nv_bfloat16 g_yh[BB * HP * WP * CK];   // ~18.9 MB
__device__ __align__(16) __nv_bfloat16 g_yl[BB * HP * WP * CK];   // ~18.9 MB
// folded weights per tap, K-major rows: [tap][o][c]
__device__ __align__(16) __nv_bfloat16 g_wh[9 * COUT * CK];
__device__ __align__(16) __nv_bfloat16 g_wl[9 * COUT * CK];

// ---------------- helpers -----------------------------------------------------
__device__ __forceinline__ uint32_t smem_u32(const void* p) {
    uint32_t a;
    asm("{ .reg .u64 t; cvta.to.shared.u64 t, %1; cvt.u32.u64 %0, t; }"
        : "=r"(a) : "l"(p));
    return a;
}
__device__ __forceinline__ void cp16(uint32_t dst, const void* src) {
    asm volatile("cp.async.ca.shared.global [%0], [%1], 16;"
                 :: "r"(dst), "l"(src) : "memory");
}
__device__ __forceinline__ void ldm4(uint32_t addr, uint32_t& r0, uint32_t& r1,
                                     uint32_t& r2, uint32_t& r3) {
    asm volatile("ldmatrix.sync.aligned.m8n8.x4.shared.b16 {%0,%1,%2,%3}, [%4];"
                 : "=r"(r0), "=r"(r1), "=r"(r2), "=r"(r3) : "r"(addr));
}
__device__ __forceinline__ void mma16816(float* c, const uint32_t* a,
                                         uint32_t b0, uint32_t b1) {
    asm volatile(
        "mma.sync.aligned.m16n8k16.row.col.f32.bf16.bf16.f32 "
        "{%0,%1,%2,%3}, {%4,%5,%6,%7}, {%8,%9}, {%0,%1,%2,%3};"
        : "+f"(c[0]), "+f"(c[1]), "+f"(c[2]), "+f"(c[3])
        : "r"(a[0]), "r"(a[1]), "r"(a[2]), "r"(a[3]), "r"(b0), "r"(b1));
}

// ---------------- kernel 1: weight fold + hi/lo split ------------------------
__global__ void wprep_kernel(const float* __restrict__ sw,
                             const float* __restrict__ sc) {
    int t = blockIdx.x * blockDim.x + threadIdx.x;
    if (t >= 9 * COUT * CK) return;
    int c = t & 511;
    int o = (t >> 9) & 63;
    int tap = t >> 15;
    int i = c >> 3, g = c & 7;
    float v = sw[((o * CIN + i) * GS + g) * 9 + tap] * sc[o * CIN + i];
    __nv_bfloat16 hb = __float2bfloat16(v);
    float r = v - __bfloat162float(hb);
    g_wh[t] = hb;
    g_wl[t] = __float2bfloat16(r);
}

// ---------------- kernel 2: B-spline basis expansion, hi/lo bf16 -------------
__global__ void basis_kernel(const float* __restrict__ x) {
    int idx = blockIdx.x * blockDim.x + threadIdx.x;
    if (idx >= BB * HP * WP * CIN) return;
    int i = idx & 63;
    int t = idx >> 6;
    int wp = t % WP; t /= WP;
    int hp = t % HP;
    int b = t / HP;

    float xv = 0.0f;
    int h = hp - 1, w = wp - 1;
    if ((unsigned)h < (unsigned)H && (unsigned)w < (unsigned)W)
        xv = x[((b * CIN + i) * H + h) * W + w];

    float gk[12];
#pragma unroll
    for (int j = 0; j < 12; j++) gk[j] = (float)(j - 3) * 0.4f - 1.0f;
    float b0[11];
#pragma unroll
    for (int j = 0; j < 11; j++)
        b0[j] = (xv >= gk[j] && xv < gk[j + 1]) ? 1.0f : 0.0f;
    float b1[10];
#pragma unroll
    for (int j = 0; j < 10; j++)
        b1[j] = ((xv - gk[j]) * b0[j] + (gk[j + 2] - xv) * b0[j + 1]) * 2.5f;
    float b2[9];
#pragma unroll
    for (int j = 0; j < 9; j++)
        b2[j] = ((xv - gk[j]) * b1[j] + (gk[j + 3] - xv) * b1[j + 1]) * 1.25f;
    float b3[8];
#pragma unroll
    for (int j = 0; j < 8; j++)
        b3[j] = ((xv - gk[j]) * b2[j] + (gk[j + 4] - xv) * b2[j + 1]) * (1.0f / 1.2f);

    unsigned short hs[8], ls[8];
#pragma unroll
    for (int g = 0; g < GS; g++) {
        float v = b3[g];
        __nv_bfloat16 hb = __float2bfloat16(v);
        float r = v - __bfloat162float(hb);
        __nv_bfloat16 lb = __float2bfloat16(r);
        hs[g] = *reinterpret_cast<unsigned short*>(&hb);
        ls[g] = *reinterpret_cast<unsigned short*>(&lb);
    }
    uint4 hv, lv;
    hv.x = (uint32_t)hs[0] | ((uint32_t)hs[1] << 16);
    hv.y = (uint32_t)hs[2] | ((uint32_t)hs[3] << 16);
    hv.z = (uint32_t)hs[4] | ((uint32_t)hs[5] << 16);
    hv.w = (uint32_t)hs[6] | ((uint32_t)hs[7] << 16);
    lv.x = (uint32_t)ls[0] | ((uint32_t)ls[1] << 16);
    lv.y = (uint32_t)ls[2] | ((uint32_t)ls[3] << 16);
    lv.z = (uint32_t)ls[4] | ((uint32_t)ls[5] << 16);
    lv.w = (uint32_t)ls[6] | ((uint32_t)ls[7] << 16);
    ((uint4*)g_yh)[idx] = hv;
    ((uint4*)g_yl)[idx] = lv;
}

// ---------------- kernel 3: mma.sync implicit-GEMM conv ----------------------
// CTA: M=128 pixels (batch b, 4 rows x 32 cols), N=64 outs, 256 thr / 8 warps.
// Warp (wm 0..3, wn 0..1): m-tile 32 (one output row), n-tile 32.
// 72 stages = 9 taps x 8 channel chunks; per stage 3 bf16-split products x 4 k16.
static constexpr int STAGE_BYTES = 49152;   // Ahi 16K | Alo 16K | Bhi 8K | Blo 8K
static constexpr int SMEM_TOTAL = 2 * STAGE_BYTES + 256;

__global__ __launch_bounds__(256, 1) void conv_kernel(float* __restrict__ out) {
    extern __shared__ char smem[];
    uint32_t sraw = smem_u32(smem);
    uint32_t sb = (sraw + 127u) & ~127u;

    int tid = threadIdx.x;
    int blk = blockIdx.x;
    int bb = blk >> 3;            // batch
    int h0 = (blk & 7) * 4;       // output row base

    int lane = tid & 31;
    int wrp = tid >> 5;
    int wm = wrp & 3, wn = wrp >> 2;
    int m0 = wm * 32, n0 = wn * 32;

    // per-thread ldmatrix row geometry
    int a_row = m0 + (lane & 7) + ((lane & 8) ? 8 : 0);       // + mt*16
    int a_seg = (lane & 16) ? 1 : 0;
    int b_rowbase = n0 + (lane & 7) + ((lane & 16) ? 8 : 0);  // + nb*16
    int b_seg = (lane & 8) ? 1 : 0;

    float acc[2][2][2][4];        // [mt][nb][fi][i]
#pragma unroll
    for (int a = 0; a < 2; a++)
#pragma unroll
        for (int b = 0; b < 2; b++)
#pragma unroll
            for (int f = 0; f < 2; f++)
#pragma unroll
                for (int i = 0; i < 4; i++) acc[a][b][f][i] = 0.0f;

    const uint4* yh4 = (const uint4*)g_yh;
    const uint4* yl4 = (const uint4*)g_yl;
    const uint4* wh4 = (const uint4*)g_wh;
    const uint4* wl4 = (const uint4*)g_wl;

    // ---- stage issue (cp.async) for iteration `it` into buffer `buf` ----
    auto issue_stage = [&](int it, int buf) {
        int tap = it >> 3;
        int ch = it & 7;
        int tk = tap / 3, tl = tap - 3 * tk;
        int c0v = ch << 3;
        uint32_t base = sb + buf * STAGE_BYTES;
#pragma unroll
        for (int k = 0; k < 8; k++) {          // A hi (k<4) / lo
            int q = tid + (k & 3) * 256;       // (row m, vec j)
            int m = q >> 3, j = q & 7;
            int hp = h0 + (m >> 5) + tk;
            int wp = (m & 31) + tl;
            const uint4* src = (k < 4) ? yh4 : yl4;
            int off = q << 4;
            off ^= (off >> 3) & 0x70;
            cp16(base + (k < 4 ? 0 : 16384) + off,
                 src + (((bb * HP + hp) * WP + wp) * 64 + c0v + j));
        }
#pragma unroll
        for (int k = 8; k < 12; k++) {         // B hi (k<10) / lo
            int q = tid + (k & 1) * 256;       // (row o, vec j)
            const uint4* src = (k < 10) ? wh4 : wl4;
            int off = q << 4;
            off ^= (off >> 3) & 0x70;
            cp16(base + (k < 10 ? 32768 : 40960) + off,
                 src + ((tap * COUT + (q >> 3)) * 64 + c0v + (q & 7)));
        }
        asm volatile("cp.async.commit_group;" ::: "memory");
    };

    // prologue: stage 0
    issue_stage(0, 0);
    asm volatile("cp.async.wait_group 0;" ::: "memory");
    __syncthreads();

    for (int it = 0; it < 72; it++) {
        int cur = it & 1;
        if (it + 1 < 72) issue_stage(it + 1, 1 - cur);

        uint32_t cbase = sb + cur * STAGE_BYTES;
#pragma unroll
        for (int p = 0; p < 3; p++) {
            uint32_t abase = cbase + (p == 2 ? 16384 : 0);
            uint32_t bbase = cbase + (p == 1 ? 40960 : 32768);
#pragma unroll
            for (int kc = 0; kc < 4; kc++) {
                uint32_t af[2][4];
#pragma unroll
                for (int mt = 0; mt < 2; mt++) {
                    int mrow = a_row + mt * 16;
                    uint32_t addr = abase + mrow * 128 +
                                    (((kc * 2 + a_seg) ^ (mrow & 7)) << 4);
                    ldm4(addr, af[mt][0], af[mt][1], af[mt][2], af[mt][3]);
                }
                uint32_t bf[2][4];
#pragma unroll
                for (int nb = 0; nb < 2; nb++) {
                    int nrow = b_rowbase + nb * 16;
                    uint32_t addr = bbase + nrow * 128 +
                                    (((kc * 2 + b_seg) ^ (nrow & 7)) << 4);
                    ldm4(addr, bf[nb][0], bf[nb][1], bf[nb][2], bf[nb][3]);
                }
#pragma unroll
                for (int mt = 0; mt < 2; mt++)
#pragma unroll
                    for (int nb = 0; nb < 2; nb++) {
                        mma16816(acc[mt][nb][0], af[mt], bf[nb][0], bf[nb][1]);
                        mma16816(acc[mt][nb][1], af[mt], bf[nb][2], bf[nb][3]);
                    }
            }
        }
        asm volatile("cp.async.wait_group 0;" ::: "memory");
        __syncthreads();
    }

    // ---- epilogue: write out[b][o][h0+wm][w] --------------------------------
    int g = lane >> 2;
    int hrow = h0 + wm;
    float* obase = out + ((size_t)bb * COUT) * (H * W) + hrow * W;
#pragma unroll
    for (int mt = 0; mt < 2; mt++)
#pragma unroll
        for (int nb = 0; nb < 2; nb++)
#pragma unroll
            for (int fi = 0; fi < 2; fi++)
#pragma unroll
                for (int i = 0; i < 4; i++) {
                    int wcol = mt * 16 + g + ((i < 2) ? 0 : 8);
                    int o = n0 + nb * 16 + fi * 8 + (lane & 3) * 2 + (i & 1);
                    obase[o * (H * W) + wcol] = acc[mt][nb][fi][i];
                }
}

// ---------------- launch ------------------------------------------------------
extern "C" void kernel_launch(void* const* d_in, const int* in_sizes, int n_in,
                              void* d_out, int out_size) {
    const float* x  = (const float*)d_in[0];   // [16,64,32,32]
    const float* sw = (const float*)d_in[1];   // [64,64,8,3,3]
    const float* sc = (const float*)d_in[2];   // [64,64]
    float* out = (float*)d_out;                // [16,64,32,32]

    static bool attr_set = false;
    if (!attr_set) {
        cudaFuncSetAttribute(conv_kernel,
                             cudaFuncAttributeMaxDynamicSharedMemorySize,
                             SMEM_TOTAL);
        attr_set = true;
    }

    {
        int n = 9 * COUT * CK;
        wprep_kernel<<<(n + 255) / 256, 256>>>(sw, sc);
    }
    {
        int n = BB * HP * WP * CIN;
        basis_kernel<<<(n + 255) / 256, 256>>>(x);
    }
    conv_kernel<<<BB * (H / 4), 256, SMEM_TOTAL>>>(out);
}

// round 6
// speedup vs baseline: 3.4724x; 1.1172x over previous
#include <cuda_runtime.h>
#include <cuda_bf16.h>
#include <cstdint>

// ---------------- problem constants -----------------------------------------
static constexpr int BB = 16, CIN = 64, H = 32, W = 32, COUT = 64;
static constexpr int GS = 8;                  // grid_size + spline_order
static constexpr int HP = 34, WP = 34;        // padded spatial
static constexpr int CK = CIN * GS;           // 512 effective channels

// ---------------- device scratch (no allocations allowed) -------------------
// basis planes, channel-last: [b][hp][wp][c=i*8+g], bf16 hi and lo parts
__device__ __align__(16) __nv_bfloat16 g_yh[BB * HP * WP * CK];   // ~18.9 MB
__device__ __align__(16) __nv_bfloat16 g_yl[BB * HP * WP * CK];   // ~18.9 MB
// folded weights per tap, K-major rows: [tap][o][c]
__device__ __align__(16) __nv_bfloat16 g_wh[9 * COUT * CK];
__device__ __align__(16) __nv_bfloat16 g_wl[9 * COUT * CK];

// ---------------- helpers -----------------------------------------------------
__device__ __forceinline__ uint32_t smem_u32(const void* p) {
    uint32_t a;
    asm("{ .reg .u64 t; cvta.to.shared.u64 t, %1; cvt.u32.u64 %0, t; }"
        : "=r"(a) : "l"(p));
    return a;
}
__device__ __forceinline__ void cp16(uint32_t dst, const void* src) {
    asm volatile("cp.async.ca.shared.global [%0], [%1], 16;"
                 :: "r"(dst), "l"(src) : "memory");
}
__device__ __forceinline__ void ldm4(uint32_t addr, uint32_t& r0, uint32_t& r1,
                                     uint32_t& r2, uint32_t& r3) {
    asm volatile("ldmatrix.sync.aligned.m8n8.x4.shared.b16 {%0,%1,%2,%3}, [%4];"
                 : "=r"(r0), "=r"(r1), "=r"(r2), "=r"(r3) : "r"(addr));
}
__device__ __forceinline__ void mma16816(float* c, const uint32_t* a,
                                         uint32_t b0, uint32_t b1) {
    asm volatile(
        "mma.sync.aligned.m16n8k16.row.col.f32.bf16.bf16.f32 "
        "{%0,%1,%2,%3}, {%4,%5,%6,%7}, {%8,%9}, {%0,%1,%2,%3};"
        : "+f"(c[0]), "+f"(c[1]), "+f"(c[2]), "+f"(c[3])
        : "r"(a[0]), "r"(a[1]), "r"(a[2]), "r"(a[3]), "r"(b0), "r"(b1));
}

// ---------------- kernel 1: weight fold + hi/lo split ------------------------
__global__ void wprep_kernel(const float* __restrict__ sw,
                             const float* __restrict__ sc) {
    int t = blockIdx.x * blockDim.x + threadIdx.x;
    if (t >= 9 * COUT * CK) return;
    int c = t & 511;
    int o = (t >> 9) & 63;
    int tap = t >> 15;
    int i = c >> 3, g = c & 7;
    float v = sw[((o * CIN + i) * GS + g) * 9 + tap] * sc[o * CIN + i];
    __nv_bfloat16 hb = __float2bfloat16(v);
    float r = v - __bfloat162float(hb);
    g_wh[t] = hb;
    g_wl[t] = __float2bfloat16(r);
}

// ---------------- kernel 2: B-spline basis expansion, hi/lo bf16 -------------
__global__ void basis_kernel(const float* __restrict__ x) {
    int idx = blockIdx.x * blockDim.x + threadIdx.x;
    if (idx >= BB * HP * WP * CIN) return;
    int i = idx & 63;
    int t = idx >> 6;
    int wp = t % WP; t /= WP;
    int hp = t % HP;
    int b = t / HP;

    float xv = 0.0f;
    int h = hp - 1, w = wp - 1;
    if ((unsigned)h < (unsigned)H && (unsigned)w < (unsigned)W)
        xv = x[((b * CIN + i) * H + h) * W + w];

    float gk[12];
#pragma unroll
    for (int j = 0; j < 12; j++) gk[j] = (float)(j - 3) * 0.4f - 1.0f;
    float b0[11];
#pragma unroll
    for (int j = 0; j < 11; j++)
        b0[j] = (xv >= gk[j] && xv < gk[j + 1]) ? 1.0f : 0.0f;
    float b1[10];
#pragma unroll
    for (int j = 0; j < 10; j++)
        b1[j] = ((xv - gk[j]) * b0[j] + (gk[j + 2] - xv) * b0[j + 1]) * 2.5f;
    float b2[9];
#pragma unroll
    for (int j = 0; j < 9; j++)
        b2[j] = ((xv - gk[j]) * b1[j] + (gk[j + 3] - xv) * b1[j + 1]) * 1.25f;
    float b3[8];
#pragma unroll
    for (int j = 0; j < 8; j++)
        b3[j] = ((xv - gk[j]) * b2[j] + (gk[j + 4] - xv) * b2[j + 1]) * (1.0f / 1.2f);

    unsigned short hs[8], ls[8];
#pragma unroll
    for (int g = 0; g < GS; g++) {
        float v = b3[g];
        __nv_bfloat16 hb = __float2bfloat16(v);
        float r = v - __bfloat162float(hb);
        __nv_bfloat16 lb = __float2bfloat16(r);
        hs[g] = *reinterpret_cast<unsigned short*>(&hb);
        ls[g] = *reinterpret_cast<unsigned short*>(&lb);
    }
    uint4 hv, lv;
    hv.x = (uint32_t)hs[0] | ((uint32_t)hs[1] << 16);
    hv.y = (uint32_t)hs[2] | ((uint32_t)hs[3] << 16);
    hv.z = (uint32_t)hs[4] | ((uint32_t)hs[5] << 16);
    hv.w = (uint32_t)hs[6] | ((uint32_t)hs[7] << 16);
    lv.x = (uint32_t)ls[0] | ((uint32_t)ls[1] << 16);
    lv.y = (uint32_t)ls[2] | ((uint32_t)ls[3] << 16);
    lv.z = (uint32_t)ls[4] | ((uint32_t)ls[5] << 16);
    lv.w = (uint32_t)ls[6] | ((uint32_t)ls[7] << 16);
    ((uint4*)g_yh)[idx] = hv;
    ((uint4*)g_yl)[idx] = lv;
}

// ---------------- kernel 3: mma.sync implicit-GEMM conv ----------------------
// CTA: M=64 pixels (batch b, 2 rows x 32 cols), N=64 outs, 128 thr / 4 warps.
// Warp (wm 0..1, wn 0..1): m-tile 32 (one output row), n-tile 32.
// 72 stages = 9 taps x 8 channel chunks; per stage 3 bf16-split products x 4 k16.
// 32KB stage, 64KB double buffer -> 3 CTAs resident per SM, grid=256.
static constexpr int STAGE_BYTES = 32768;   // Ahi 8K | Alo 8K | Bhi 8K | Blo 8K
static constexpr int SMEM_TOTAL = 2 * STAGE_BYTES + 256;

__global__ __launch_bounds__(128, 3) void conv_kernel(float* __restrict__ out) {
    extern __shared__ char smem[];
    uint32_t sraw = smem_u32(smem);
    uint32_t sb = (sraw + 127u) & ~127u;

    int tid = threadIdx.x;
    int blk = blockIdx.x;
    int bb = blk >> 4;            // batch
    int h0 = (blk & 15) * 2;      // output row base

    int lane = tid & 31;
    int wrp = tid >> 5;
    int wm = wrp & 1, wn = wrp >> 1;
    int m0 = wm * 32, n0 = wn * 32;

    // per-thread ldmatrix row geometry
    int a_row = m0 + (lane & 7) + ((lane & 8) ? 8 : 0);       // + mt*16
    int a_seg = (lane & 16) ? 1 : 0;
    int b_rowbase = n0 + (lane & 7) + ((lane & 16) ? 8 : 0);  // + nb*16
    int b_seg = (lane & 8) ? 1 : 0;

    float acc[2][2][2][4];        // [mt][nb][fi][i]
#pragma unroll
    for (int a = 0; a < 2; a++)
#pragma unroll
        for (int b = 0; b < 2; b++)
#pragma unroll
            for (int f = 0; f < 2; f++)
#pragma unroll
                for (int i = 0; i < 4; i++) acc[a][b][f][i] = 0.0f;

    const uint4* yh4 = (const uint4*)g_yh;
    const uint4* yl4 = (const uint4*)g_yl;
    const uint4* wh4 = (const uint4*)g_wh;
    const uint4* wl4 = (const uint4*)g_wl;

    // ---- stage issue (cp.async) for iteration `it` into buffer `buf` ----
    auto issue_stage = [&](int it, int buf) {
        int tap = it >> 3;
        int ch = it & 7;
        int tk = tap / 3, tl = tap - 3 * tk;
        int c0v = ch << 3;
        uint32_t base = sb + buf * STAGE_BYTES;
#pragma unroll
        for (int k = 0; k < 8; k++) {          // A hi (k<4) / lo
            int q = tid + (k & 3) * 128;       // 0..511: (row m, vec j)
            int m = q >> 3, j = q & 7;
            int hp = h0 + (m >> 5) + tk;       // m>>5 in {0,1}
            int wp = (m & 31) + tl;
            const uint4* src = (k < 4) ? yh4 : yl4;
            int off = q << 4;
            off ^= (off >> 3) & 0x70;
            cp16(base + (k < 4 ? 0 : 8192) + off,
                 src + (((bb * HP + hp) * WP + wp) * 64 + c0v + j));
        }
#pragma unroll
        for (int k = 0; k < 8; k++) {          // B hi (k<4) / lo
            int q = tid + (k & 3) * 128;       // 0..511: (row o, vec j)
            const uint4* src = (k < 4) ? wh4 : wl4;
            int off = q << 4;
            off ^= (off >> 3) & 0x70;
            cp16(base + 16384 + (k < 4 ? 0 : 8192) + off,
                 src + ((tap * COUT + (q >> 3)) * 64 + c0v + (q & 7)));
        }
        asm volatile("cp.async.commit_group;" ::: "memory");
    };

    // prologue: stage 0
    issue_stage(0, 0);
    asm volatile("cp.async.wait_group 0;" ::: "memory");
    __syncthreads();

    for (int it = 0; it < 72; it++) {
        int cur = it & 1;
        if (it + 1 < 72) issue_stage(it + 1, 1 - cur);

        uint32_t cbase = sb + cur * STAGE_BYTES;
#pragma unroll
        for (int p = 0; p < 3; p++) {
            uint32_t abase = cbase + (p == 2 ? 8192 : 0);
            uint32_t bbase = cbase + 16384 + (p == 1 ? 8192 : 0);
#pragma unroll
            for (int kc = 0; kc < 4; kc++) {
                uint32_t af[2][4];
#pragma unroll
                for (int mt = 0; mt < 2; mt++) {
                    int mrow = a_row + mt * 16;
                    uint32_t addr = abase + mrow * 128 +
                                    (((kc * 2 + a_seg) ^ (mrow & 7)) << 4);
                    ldm4(addr, af[mt][0], af[mt][1], af[mt][2], af[mt][3]);
                }
                uint32_t bf[2][4];
#pragma unroll
                for (int nb = 0; nb < 2; nb++) {
                    int nrow = b_rowbase + nb * 16;
                    uint32_t addr = bbase + nrow * 128 +
                                    (((kc * 2 + b_seg) ^ (nrow & 7)) << 4);
                    ldm4(addr, bf[nb][0], bf[nb][1], bf[nb][2], bf[nb][3]);
                }
#pragma unroll
                for (int mt = 0; mt < 2; mt++)
#pragma unroll
                    for (int nb = 0; nb < 2; nb++) {
                        mma16816(acc[mt][nb][0], af[mt], bf[nb][0], bf[nb][1]);
                        mma16816(acc[mt][nb][1], af[mt], bf[nb][2], bf[nb][3]);
                    }
            }
        }
        asm volatile("cp.async.wait_group 0;" ::: "memory");
        __syncthreads();
    }

    // ---- epilogue: write out[b][o][h0+wm][w] --------------------------------
    int g = lane >> 2;
    int hrow = h0 + wm;
    float* obase = out + ((size_t)bb * COUT) * (H * W) + hrow * W;
#pragma unroll
    for (int mt = 0; mt < 2; mt++)
#pragma unroll
        for (int nb = 0; nb < 2; nb++)
#pragma unroll
            for (int fi = 0; fi < 2; fi++)
#pragma unroll
                for (int i = 0; i < 4; i++) {
                    int wcol = mt * 16 + g + ((i < 2) ? 0 : 8);
                    int o = n0 + nb * 16 + fi * 8 + (lane & 3) * 2 + (i & 1);
                    obase[o * (H * W) + wcol] = acc[mt][nb][fi][i];
                }
}

// ---------------- launch ------------------------------------------------------
extern "C" void kernel_launch(void* const* d_in, const int* in_sizes, int n_in,
                              void* d_out, int out_size) {
    const float* x  = (const float*)d_in[0];   // [16,64,32,32]
    const float* sw = (const float*)d_in[1];   // [64,64,8,3,3]
    const float* sc = (const float*)d_in[2];   // [64,64]
    float* out = (float*)d_out;                // [16,64,32,32]

    cudaFuncSetAttribute(conv_kernel,
                         cudaFuncAttributeMaxDynamicSharedMemorySize,
                         SMEM_TOTAL);

    {
        int n = 9 * COUT * CK;
        wprep_kernel<<<(n + 255) / 256, 256>>>(sw, sc);
    }
    {
        int n = BB * HP * WP * CIN;
        basis_kernel<<<(n + 255) / 256, 256>>>(x);
    }
    conv_kernel<<<BB * (H / 2), 128, SMEM_TOTAL>>>(out);
}

// round 7
// speedup vs baseline: 3.5263x; 1.0155x over previous
#include <cuda_runtime.h>
#include <cuda_bf16.h>
#include <cstdint>

// ---------------- problem constants -----------------------------------------
static constexpr int BB = 16, CIN = 64, H = 32, W = 32, COUT = 64;
static constexpr int GS = 8;                  // grid_size + spline_order
static constexpr int HP = 34, WP = 34;        // padded spatial
static constexpr int CK = CIN * GS;           // 512 effective channels

// ---------------- device scratch (no allocations allowed) -------------------
// basis planes, channel-last, tf32-rounded fp32, k-permuted within each 8-block:
// [b][hp][wp][c']  where slot(g) = ((g<<1)&7)|(g>>2)  (pairs (t,t+4) adjacent)
__device__ __align__(16) float g_yf[BB * HP * WP * CK];   // ~37.9 MB
// folded weights, tf32-rounded fp32, same k permutation: [tap][o][c']
__device__ __align__(16) float g_wt[9 * COUT * CK];

// ---------------- helpers -----------------------------------------------------
__device__ __forceinline__ uint32_t smem_u32(const void* p) {
    uint32_t a;
    asm("{ .reg .u64 t; cvta.to.shared.u64 t, %1; cvt.u32.u64 %0, t; }"
        : "=r"(a) : "l"(p));
    return a;
}
__device__ __forceinline__ void cp16(uint32_t dst, const void* src) {
    asm volatile("cp.async.ca.shared.global [%0], [%1], 16;"
                 :: "r"(dst), "l"(src) : "memory");
}
__device__ __forceinline__ void lds64(uint32_t addr, uint32_t& r0, uint32_t& r1) {
    asm volatile("ld.shared.v2.b32 {%0,%1}, [%2];"
                 : "=r"(r0), "=r"(r1) : "r"(addr));
}
__device__ __forceinline__ void mma1688(float* c, uint32_t a0, uint32_t a1,
                                        uint32_t a2, uint32_t a3,
                                        uint32_t b0, uint32_t b1) {
    asm volatile(
        "mma.sync.aligned.m16n8k8.row.col.f32.tf32.tf32.f32 "
        "{%0,%1,%2,%3}, {%4,%5,%6,%7}, {%8,%9}, {%0,%1,%2,%3};"
        : "+f"(c[0]), "+f"(c[1]), "+f"(c[2]), "+f"(c[3])
        : "r"(a0), "r"(a1), "r"(a2), "r"(a3), "r"(b0), "r"(b1));
}
__device__ __forceinline__ float tf32r(float v) {
    uint32_t u;
    asm("cvt.rna.tf32.f32 %0, %1;" : "=r"(u) : "f"(v));
    return __uint_as_float(u);
}

// ---------------- kernel 1: weight fold + tf32 round + k-permute ------------
__global__ void wprep_kernel(const float* __restrict__ sw,
                             const float* __restrict__ sc) {
    int t = blockIdx.x * blockDim.x + threadIdx.x;
    if (t >= 9 * COUT * CK) return;
    int c = t & 511;
    int o = (t >> 9) & 63;
    int tap = t >> 15;
    int i = c >> 3, g = c & 7;
    float v = sw[((o * CIN + i) * GS + g) * 9 + tap] * sc[o * CIN + i];
    int slot = ((g << 1) & 7) | (g >> 2);        // k-permute within 8-block
    g_wt[(t & ~7) | slot] = tf32r(v);
}

// ---------------- kernel 2: B-spline basis, tf32 fp32, k-permuted ------------
__global__ void basis_kernel(const float* __restrict__ x) {
    int idx = blockIdx.x * blockDim.x + threadIdx.x;
    if (idx >= BB * HP * WP * CIN) return;
    int i = idx & 63;
    int t = idx >> 6;
    int wp = t % WP; t /= WP;
    int hp = t % HP;
    int b = t / HP;

    float xv = 0.0f;
    int h = hp - 1, w = wp - 1;
    if ((unsigned)h < (unsigned)H && (unsigned)w < (unsigned)W)
        xv = x[((b * CIN + i) * H + h) * W + w];

    float gk[12];
#pragma unroll
    for (int j = 0; j < 12; j++) gk[j] = (float)(j - 3) * 0.4f - 1.0f;
    float b0[11];
#pragma unroll
    for (int j = 0; j < 11; j++)
        b0[j] = (xv >= gk[j] && xv < gk[j + 1]) ? 1.0f : 0.0f;
    float b1[10];
#pragma unroll
    for (int j = 0; j < 10; j++)
        b1[j] = ((xv - gk[j]) * b0[j] + (gk[j + 2] - xv) * b0[j + 1]) * 2.5f;
    float b2[9];
#pragma unroll
    for (int j = 0; j < 9; j++)
        b2[j] = ((xv - gk[j]) * b1[j] + (gk[j + 3] - xv) * b1[j + 1]) * 1.25f;
    float b3[8];
#pragma unroll
    for (int j = 0; j < 8; j++)
        b3[j] = ((xv - gk[j]) * b2[j] + (gk[j + 4] - xv) * b2[j + 1]) * (1.0f / 1.2f);

    float f[8];
#pragma unroll
    for (int g = 0; g < GS; g++) {
        int slot = ((g << 1) & 7) | (g >> 2);
        f[slot] = tf32r(b3[g]);
    }
    float4* dst = (float4*)(g_yf + (size_t)idx * 8);
    dst[0] = make_float4(f[0], f[1], f[2], f[3]);
    dst[1] = make_float4(f[4], f[5], f[6], f[7]);
}

// ---------------- kernel 3: tf32 mma.sync implicit-GEMM conv -----------------
// CTA: M=64 pixels (batch b, 2 rows x 32 cols), N=64 outs, 128 thr / 4 warps.
// Warp (wm 0..1, wn 0..1): m-tile 32 (one output row), n-tile 32.
// 72 stages = 9 taps x 8 channel chunks (64 ch); per stage per warp:
// 8 k8-steps x (4 LDS.64 A + 4 LDS.64 B... grouped) + 64 HMMA.1688.
static constexpr int STAGE_BYTES = 32768;   // A 16K | B 16K (fp32)
static constexpr int SMEM_TOTAL = 2 * STAGE_BYTES + 256;

__global__ __launch_bounds__(128, 3) void conv_kernel(float* __restrict__ out) {
    extern __shared__ char smem[];
    uint32_t sraw = smem_u32(smem);
    uint32_t sb = (sraw + 255u) & ~255u;

    int tid = threadIdx.x;
    int blk = blockIdx.x;
    int bb = blk >> 4;            // batch
    int h0 = (blk & 15) * 2;      // output row base

    int lane = tid & 31;
    int wrp = tid >> 5;
    int wm = wrp & 1, wn = wrp >> 1;
    int m0w = wm * 32, n0w = wn * 32;
    int g = lane >> 2, t4 = lane & 3;

    // smem byte offsets (before kstep XOR), swizzle key = row&7 = g everywhere
    // addr(m) = m*256 + t4*8 + (g<<5), then ^ (kstep<<5)
    uint32_t aoff[2][2];          // [mt][half(row+8)]
#pragma unroll
    for (int mt = 0; mt < 2; mt++)
#pragma unroll
        for (int hf = 0; hf < 2; hf++)
            aoff[mt][hf] = (uint32_t)((m0w + mt * 16 + g + hf * 8) * 256 +
                                      t4 * 8 + (g << 5));
    uint32_t boff[4];
#pragma unroll
    for (int nf = 0; nf < 4; nf++)
        boff[nf] = (uint32_t)((n0w + nf * 8 + g) * 256 + t4 * 8 + (g << 5));

    float acc[2][4][4];           // [mt][nf][i]
#pragma unroll
    for (int a = 0; a < 2; a++)
#pragma unroll
        for (int b = 0; b < 4; b++)
#pragma unroll
            for (int i = 0; i < 4; i++) acc[a][b][i] = 0.0f;

    const uint4* yf4 = (const uint4*)g_yf;
    const uint4* wt4 = (const uint4*)g_wt;

    // ---- stage issue (cp.async) for iteration `it` into buffer `buf` ----
    auto issue_stage = [&](int it, int buf) {
        int tap = it >> 3;
        int ch = it & 7;
        int tk = tap / 3, tl = tap - 3 * tk;
        int cw0 = ch * 16;                 // chunk offset in uint4 units
        uint32_t base = sb + buf * STAGE_BYTES;
#pragma unroll
        for (int k = 0; k < 8; k++) {      // A: 1024 16B chunks
            int q = tid + k * 128;
            int m = q >> 4, c4 = q & 15;
            int hp = h0 + (m >> 5) + tk;
            int wp = (m & 31) + tl;
            uint32_t dst = base + m * 256 + ((c4 ^ ((m & 7) << 1)) << 4);
            cp16(dst, yf4 + (((bb * HP + hp) * WP + wp) * 128 + cw0 + c4));
        }
#pragma unroll
        for (int k = 0; k < 8; k++) {      // B: 1024 16B chunks
            int q = tid + k * 128;
            int o = q >> 4, c4 = q & 15;
            uint32_t dst = base + 16384 + o * 256 + ((c4 ^ ((o & 7) << 1)) << 4);
            cp16(dst, wt4 + ((tap * COUT + o) * 128 + cw0 + c4));
        }
        asm volatile("cp.async.commit_group;" ::: "memory");
    };

    // prologue
    issue_stage(0, 0);
    asm volatile("cp.async.wait_group 0;" ::: "memory");
    __syncthreads();

    for (int it = 0; it < 72; it++) {
        int cur = it & 1;
        if (it + 1 < 72) issue_stage(it + 1, 1 - cur);

        uint32_t abase = sb + cur * STAGE_BYTES;
        uint32_t bbase = abase + 16384;
#pragma unroll
        for (int ks = 0; ks < 8; ks++) {
            uint32_t xo = (uint32_t)(ks << 5);
            uint32_t a0[2], a1[2], a2[2], a3[2];
#pragma unroll
            for (int mt = 0; mt < 2; mt++) {
                lds64(abase + (aoff[mt][0] ^ xo), a0[mt], a2[mt]);
                lds64(abase + (aoff[mt][1] ^ xo), a1[mt], a3[mt]);
            }
            uint32_t b0[4], b1[4];
#pragma unroll
            for (int nf = 0; nf < 4; nf++)
                lds64(bbase + (boff[nf] ^ xo), b0[nf], b1[nf]);
#pragma unroll
            for (int mt = 0; mt < 2; mt++)
#pragma unroll
                for (int nf = 0; nf < 4; nf++)
                    mma1688(acc[mt][nf], a0[mt], a1[mt], a2[mt], a3[mt],
                            b0[nf], b1[nf]);
        }
        asm volatile("cp.async.wait_group 0;" ::: "memory");
        __syncthreads();
    }

    // ---- epilogue: write out[b][o][h0+wm][wcol] -----------------------------
    int hrow = h0 + wm;
    float* obase = out + ((size_t)bb * COUT) * (H * W) + hrow * W;
#pragma unroll
    for (int mt = 0; mt < 2; mt++) {
        int wcol = mt * 16 + g;
#pragma unroll
        for (int nf = 0; nf < 4; nf++) {
            int o = n0w + nf * 8 + 2 * t4;
            obase[o * (H * W) + wcol]           = acc[mt][nf][0];
            obase[(o + 1) * (H * W) + wcol]     = acc[mt][nf][1];
            obase[o * (H * W) + wcol + 8]       = acc[mt][nf][2];
            obase[(o + 1) * (H * W) + wcol + 8] = acc[mt][nf][3];
        }
    }
}

// ---------------- launch ------------------------------------------------------
extern "C" void kernel_launch(void* const* d_in, const int* in_sizes, int n_in,
                              void* d_out, int out_size) {
    const float* x  = (const float*)d_in[0];   // [16,64,32,32]
    const float* sw = (const float*)d_in[1];   // [64,64,8,3,3]
    const float* sc = (const float*)d_in[2];   // [64,64]
    float* out = (float*)d_out;                // [16,64,32,32]

    cudaFuncSetAttribute(conv_kernel,
                         cudaFuncAttributeMaxDynamicSharedMemorySize,
                         SMEM_TOTAL);

    {
        int n = 9 * COUT * CK;
        wprep_kernel<<<(n + 255) / 256, 256>>>(sw, sc);
    }
    {
        int n = BB * HP * WP * CIN;
        basis_kernel<<<(n + 255) / 256, 256>>>(x);
    }
    conv_kernel<<<BB * (H / 2), 128, SMEM_TOTAL>>>(out);
}

// round 8
// speedup vs baseline: 3.9542x; 1.1214x over previous
#include <cuda_runtime.h>
#include <cuda_bf16.h>
#include <cstdint>

// ---------------- problem constants -----------------------------------------
static constexpr int BB = 16, CIN = 64, H = 32, W = 32, COUT = 64;
static constexpr int GS = 8;                  // grid_size + spline_order
static constexpr int HP = 34, WP = 34;        // padded spatial
static constexpr int CK = CIN * GS;           // 512 effective channels

// ---------------- device scratch (no allocations allowed) -------------------
// basis planes, channel-last, tf32-rounded fp32, k-permuted within each 8-block:
// [b][hp][wp][c']  where slot(g) = ((g<<1)&7)|(g>>2)  (pairs (t,t+4) adjacent)
__device__ __align__(16) float g_yf[BB * HP * WP * CK];   // ~37.9 MB
// folded weights, tf32-rounded fp32, same k permutation: [tap][o][c']
__device__ __align__(16) float g_wt[9 * COUT * CK];

// ---------------- helpers -----------------------------------------------------
__device__ __forceinline__ uint32_t smem_u32(const void* p) {
    uint32_t a;
    asm("{ .reg .u64 t; cvta.to.shared.u64 t, %1; cvt.u32.u64 %0, t; }"
        : "=r"(a) : "l"(p));
    return a;
}
__device__ __forceinline__ void cp16(uint32_t dst, const void* src) {
    asm volatile("cp.async.ca.shared.global [%0], [%1], 16;"
                 :: "r"(dst), "l"(src) : "memory");
}
__device__ __forceinline__ void lds64(uint32_t addr, uint32_t& r0, uint32_t& r1) {
    asm volatile("ld.shared.v2.b32 {%0,%1}, [%2];"
                 : "=r"(r0), "=r"(r1) : "r"(addr));
}
__device__ __forceinline__ void mma1688(float* c, uint32_t a0, uint32_t a1,
                                        uint32_t a2, uint32_t a3,
                                        uint32_t b0, uint32_t b1) {
    asm volatile(
        "mma.sync.aligned.m16n8k8.row.col.f32.tf32.tf32.f32 "
        "{%0,%1,%2,%3}, {%4,%5,%6,%7}, {%8,%9}, {%0,%1,%2,%3};"
        : "+f"(c[0]), "+f"(c[1]), "+f"(c[2]), "+f"(c[3])
        : "r"(a0), "r"(a1), "r"(a2), "r"(a3), "r"(b0), "r"(b1));
}
__device__ __forceinline__ float tf32r(float v) {
    uint32_t u;
    asm("cvt.rna.tf32.f32 %0, %1;" : "=r"(u) : "f"(v));
    return __uint_as_float(u);
}

// ---------------- kernel 1: weight fold + tf32 round + k-permute ------------
__global__ void wprep_kernel(const float* __restrict__ sw,
                             const float* __restrict__ sc) {
    int t = blockIdx.x * blockDim.x + threadIdx.x;
    if (t >= 9 * COUT * CK) return;
    int c = t & 511;
    int o = (t >> 9) & 63;
    int tap = t >> 15;
    int i = c >> 3, g = c & 7;
    float v = sw[((o * CIN + i) * GS + g) * 9 + tap] * sc[o * CIN + i];
    int slot = ((g << 1) & 7) | (g >> 2);        // k-permute within 8-block
    g_wt[(t & ~7) | slot] = tf32r(v);
}

// ---------------- kernel 2: B-spline basis, tf32 fp32, k-permuted ------------
__global__ void basis_kernel(const float* __restrict__ x) {
    int idx = blockIdx.x * blockDim.x + threadIdx.x;
    if (idx >= BB * HP * WP * CIN) return;
    int i = idx & 63;
    int t = idx >> 6;
    int wp = t % WP; t /= WP;
    int hp = t % HP;
    int b = t / HP;

    float xv = 0.0f;
    int h = hp - 1, w = wp - 1;
    if ((unsigned)h < (unsigned)H && (unsigned)w < (unsigned)W)
        xv = x[((b * CIN + i) * H + h) * W + w];

    float gk[12];
#pragma unroll
    for (int j = 0; j < 12; j++) gk[j] = (float)(j - 3) * 0.4f - 1.0f;
    float b0[11];
#pragma unroll
    for (int j = 0; j < 11; j++)
        b0[j] = (xv >= gk[j] && xv < gk[j + 1]) ? 1.0f : 0.0f;
    float b1[10];
#pragma unroll
    for (int j = 0; j < 10; j++)
        b1[j] = ((xv - gk[j]) * b0[j] + (gk[j + 2] - xv) * b0[j + 1]) * 2.5f;
    float b2[9];
#pragma unroll
    for (int j = 0; j < 9; j++)
        b2[j] = ((xv - gk[j]) * b1[j] + (gk[j + 3] - xv) * b1[j + 1]) * 1.25f;
    float b3[8];
#pragma unroll
    for (int j = 0; j < 8; j++)
        b3[j] = ((xv - gk[j]) * b2[j] + (gk[j + 4] - xv) * b2[j + 1]) * (1.0f / 1.2f);

    float f[8];
#pragma unroll
    for (int g = 0; g < GS; g++) {
        int slot = ((g << 1) & 7) | (g >> 2);
        f[slot] = tf32r(b3[g]);
    }
    float4* dst = (float4*)(g_yf + (size_t)idx * 8);
    dst[0] = make_float4(f[0], f[1], f[2], f[3]);
    dst[1] = make_float4(f[4], f[5], f[6], f[7]);
}

// ---------------- kernel 3: tf32 mma.sync conv, A reused across taps ---------
// CTA: M=64 pixels (batch b, 2 rows x 32 cols), N=64 outs, 128 thr / 4 warps.
// Chunk-major K loop: per 64-ch chunk, stage A block (4 rows x 34 cols x 64ch,
// 34.8 KB) ONCE; run all 9 taps from it with shifted smem addressing. B (16 KB
// per tap) double-buffered. Traffic: 590 MB -> 366 MB.
static constexpr int A_BYTES = 136 * 256;        // 34816
static constexpr int B_BYTES = 16384;
static constexpr int SMEM_TOTAL = A_BYTES + 2 * B_BYTES + 256;

__global__ __launch_bounds__(128, 3) void conv_kernel(float* __restrict__ out) {
    extern __shared__ char smem[];
    uint32_t sraw = smem_u32(smem);
    uint32_t sb = (sraw + 255u) & ~255u;
    uint32_t Ab = sb;
    uint32_t Bb0 = sb + A_BYTES;

    int tid = threadIdx.x;
    int blk = blockIdx.x;
    int bb = blk >> 4;            // batch
    int h0 = (blk & 15) * 2;      // output row base

    int lane = tid & 31;
    int wrp = tid >> 5;
    int wm = wrp & 1, wn = wrp >> 1;
    int n0w = wn * 32;
    int g = lane >> 2, t4 = lane & 3;

    // B smem offsets (XOR ks<<5 at use): row o = n0w + nf*8 + g, key = g
    uint32_t boff[4];
#pragma unroll
    for (int nf = 0; nf < 4; nf++)
        boff[nf] = (uint32_t)((n0w + nf * 8 + g) * 256 + t4 * 8 + (g << 5));

    float acc[2][4][4];           // [mt][nf][i]
#pragma unroll
    for (int a = 0; a < 2; a++)
#pragma unroll
        for (int b = 0; b < 4; b++)
#pragma unroll
            for (int i = 0; i < 4; i++) acc[a][b][i] = 0.0f;

    const uint4* yf4 = (const uint4*)g_yf;
    const uint4* wt4 = (const uint4*)g_wt;

    // ---- A block stage: 4 rows x 34 cols x 64 ch of chunk `ch` --------------
    auto issueA = [&](int ch) {
        int cw0 = ch * 16;
#pragma unroll
        for (int k = 0; k < 17; k++) {
            int q = tid + k * 128;             // 0..2175
            int pix = q >> 4, c4 = q & 15;
            int r = pix / 34, wp = pix - r * 34;
            uint32_t dst = Ab + pix * 256 + ((c4 ^ ((pix & 7) << 1)) << 4);
            cp16(dst, yf4 + (((bb * HP + h0 + r) * WP + wp) * 128 + cw0 + c4));
        }
    };
    // ---- B tile stage: tap `tap`, chunk `ch` into buffer `buf` --------------
    auto issueB = [&](int tap, int ch, int buf) {
        int cw0 = ch * 16;
        uint32_t base = Bb0 + buf * B_BYTES;
#pragma unroll
        for (int k = 0; k < 8; k++) {
            int q = tid + k * 128;             // 0..1023
            int o = q >> 4, c4 = q & 15;
            uint32_t dst = base + o * 256 + ((c4 ^ ((o & 7) << 1)) << 4);
            cp16(dst, wt4 + ((tap * COUT + o) * 128 + cw0 + c4));
        }
    };

    // ---- compute one tap from resident A + B buffer -------------------------
    auto compute = [&](int tap, int buf) {
        int tk = tap / 3, tl = tap - 3 * tk;
        int prow = wm + tk;
        uint32_t apx[2][2];       // [mt][hf]: base addr incl key<<5
#pragma unroll
        for (int mt = 0; mt < 2; mt++)
#pragma unroll
            for (int hf = 0; hf < 2; hf++) {
                int p = prow * 34 + mt * 16 + g + hf * 8 + tl;
                apx[mt][hf] = (uint32_t)(p * 256 + t4 * 8 + ((p & 7) << 5));
            }
        uint32_t bbase = Bb0 + buf * B_BYTES;
#pragma unroll
        for (int ks = 0; ks < 8; ks++) {
            uint32_t xo = (uint32_t)(ks << 5);
            uint32_t a0[2], a1[2], a2[2], a3[2];
#pragma unroll
            for (int mt = 0; mt < 2; mt++) {
                lds64(Ab + (apx[mt][0] ^ xo), a0[mt], a2[mt]);
                lds64(Ab + (apx[mt][1] ^ xo), a1[mt], a3[mt]);
            }
            uint32_t b0[4], b1[4];
#pragma unroll
            for (int nf = 0; nf < 4; nf++)
                lds64(bbase + (boff[nf] ^ xo), b0[nf], b1[nf]);
#pragma unroll
            for (int mt = 0; mt < 2; mt++)
#pragma unroll
                for (int nf = 0; nf < 4; nf++)
                    mma1688(acc[mt][nf], a0[mt], a1[mt], a2[mt], a3[mt],
                            b0[nf], b1[nf]);
        }
    };

    // ---- pipeline -----------------------------------------------------------
    issueA(0);
    issueB(0, 0, 0);
    asm volatile("cp.async.commit_group;" ::: "memory");
    asm volatile("cp.async.wait_group 0;" ::: "memory");
    __syncthreads();

    int cur = 0;
    for (int ch = 0; ch < 8; ch++) {
        for (int tap = 0; tap < 9; tap++) {
            bool hn = (tap < 8);
            if (hn) {
                issueB(tap + 1, ch, cur ^ 1);
                asm volatile("cp.async.commit_group;" ::: "memory");
            }
            compute(tap, cur);
            if (hn) asm volatile("cp.async.wait_group 0;" ::: "memory");
            __syncthreads();
            if (hn) cur ^= 1;
        }
        if (ch < 7) {
            issueA(ch + 1);
            issueB(0, ch + 1, cur ^ 1);
            asm volatile("cp.async.commit_group;" ::: "memory");
            asm volatile("cp.async.wait_group 0;" ::: "memory");
            __syncthreads();
            cur ^= 1;
        }
    }

    // ---- epilogue: write out[b][o][h0+wm][wcol] -----------------------------
    int hrow = h0 + wm;
    float* obase = out + ((size_t)bb * COUT) * (H * W) + hrow * W;
#pragma unroll
    for (int mt = 0; mt < 2; mt++) {
        int wcol = mt * 16 + g;
#pragma unroll
        for (int nf = 0; nf < 4; nf++) {
            int o = n0w + nf * 8 + 2 * t4;
            obase[o * (H * W) + wcol]           = acc[mt][nf][0];
            obase[(o + 1) * (H * W) + wcol]     = acc[mt][nf][1];
            obase[o * (H * W) + wcol + 8]       = acc[mt][nf][2];
            obase[(o + 1) * (H * W) + wcol + 8] = acc[mt][nf][3];
        }
    }
}

// ---------------- launch ------------------------------------------------------
extern "C" void kernel_launch(void* const* d_in, const int* in_sizes, int n_in,
                              void* d_out, int out_size) {
    const float* x  = (const float*)d_in[0];   // [16,64,32,32]
    const float* sw = (const float*)d_in[1];   // [64,64,8,3,3]
    const float* sc = (const float*)d_in[2];   // [64,64]
    float* out = (float*)d_out;                // [16,64,32,32]

    cudaFuncSetAttribute(conv_kernel,
                         cudaFuncAttributeMaxDynamicSharedMemorySize,
                         SMEM_TOTAL);

    {
        int n = 9 * COUT * CK;
        wprep_kernel<<<(n + 255) / 256, 256>>>(sw, sc);
    }
    {
        int n = BB * HP * WP * CIN;
        basis_kernel<<<(n + 255) / 256, 256>>>(x);
    }
    conv_kernel<<<BB * (H / 2), 128, SMEM_TOTAL>>>(out);
}